// round 13
// baseline (speedup 1.0000x reference)
#include <cuda_runtime.h>
#include <cuda_bf16.h>
#include <math.h>

#define B_  4
#define S_  2048
#define D_  1024
#define H_  16
#define DH_ 64
#define M_  (B_*S_)          // 8192 rows

typedef unsigned long long u64;
typedef unsigned int u32;

// ---------------- helpers ----------------------------------------
__device__ __forceinline__ u32 smem_u32(const void* p) {
    u32 a;
    asm("{ .reg .u64 t; cvta.to.shared.u64 t, %1; cvt.u32.u64 %0, t; }"
        : "=r"(a) : "l"(p));
    return a;
}
__device__ __forceinline__ void ldmx4(u32* r, u32 addr) {
    asm volatile("ldmatrix.sync.aligned.m8n8.x4.shared.b16 {%0,%1,%2,%3}, [%4];"
                 : "=r"(r[0]), "=r"(r[1]), "=r"(r[2]), "=r"(r[3]) : "r"(addr));
}
__device__ __forceinline__ void ldmx4t(u32* r, u32 addr) {
    asm volatile("ldmatrix.sync.aligned.m8n8.x4.trans.shared.b16 {%0,%1,%2,%3}, [%4];"
                 : "=r"(r[0]), "=r"(r[1]), "=r"(r[2]), "=r"(r[3]) : "r"(addr));
}
__device__ __forceinline__ void mma_bf16(float* c, const u32* a, u32 b0, u32 b1) {
    asm volatile(
        "mma.sync.aligned.m16n8k16.row.col.f32.bf16.bf16.f32 "
        "{%0,%1,%2,%3}, {%4,%5,%6,%7}, {%8,%9}, {%0,%1,%2,%3};"
        : "+f"(c[0]), "+f"(c[1]), "+f"(c[2]), "+f"(c[3])
        : "r"(a[0]), "r"(a[1]), "r"(a[2]), "r"(a[3]), "r"(b0), "r"(b1));
}
__device__ __forceinline__ u32 pkbf(float lo, float hi) {
    u32 r; asm("cvt.rn.bf16x2.f32 %0, %2, %1;" : "=r"(r) : "f"(lo), "f"(hi)); return r;
}
__device__ __forceinline__ float ex2f(float x) {
    float y; asm("ex2.approx.ftz.f32 %0, %1;" : "=f"(y) : "f"(x)); return y;
}
__device__ __forceinline__ float bf16rt(float v) {
    return __bfloat162float(__float2bfloat16(v));
}
__device__ __forceinline__ void cpa16(u32 dst, const void* src) {
    asm volatile("cp.async.cg.shared.global [%0], [%1], 16;"
                 :: "r"(dst), "l"(__cvta_generic_to_global(src)) : "memory");
}
__device__ __forceinline__ void cp_commit() {
    asm volatile("cp.async.commit_group;" ::: "memory");
}
__device__ __forceinline__ void cp_wait0() {
    asm volatile("cp.async.wait_group 0;" ::: "memory");
}

// ---------------- scratch (no allocations allowed) ----------------
__device__ float g_res[(size_t)M_*D_];               // pre-layernorm
__device__ __nv_bfloat16 g_x_hi[(size_t)M_*D_];
__device__ __nv_bfloat16 g_x_lo[(size_t)M_*D_];
__device__ __nv_bfloat16 g_wt_hi[(size_t)4096*1024]; // [n][k]: 0-3071 WQKV^T, 3072-4095 WO^T
__device__ __nv_bfloat16 g_wt_lo[(size_t)4096*1024];
__device__ __nv_bfloat16 g_qh[(size_t)B_*H_*S_*DH_]; // [B,H,S,DH], q pre-scaled 0.125*log2e
__device__ __nv_bfloat16 g_ql[(size_t)B_*H_*S_*DH_];
__device__ __nv_bfloat16 g_kh[(size_t)B_*H_*S_*DH_];
__device__ __nv_bfloat16 g_kl[(size_t)B_*H_*S_*DH_];
__device__ __nv_bfloat16 g_vh[(size_t)B_*H_*S_*DH_];
__device__ __nv_bfloat16 g_vl[(size_t)B_*H_*S_*DH_];
__device__ __nv_bfloat16 g_cx_hi[(size_t)M_*D_];     // ctx split [m][k]
__device__ __nv_bfloat16 g_cx_lo[(size_t)M_*D_];

// =================================================================
// Prep: split x into bf16 hi/lo
// =================================================================
__global__ __launch_bounds__(256) void split_x(const float* __restrict__ x)
{
    size_t i = (size_t)blockIdx.x * 1024 + threadIdx.x * 4;
    float4 v = *(const float4*)(x + i);
    float h0 = bf16rt(v.x), h1 = bf16rt(v.y), h2 = bf16rt(v.z), h3 = bf16rt(v.w);
    *(u32*)(g_x_hi + i)     = pkbf(h0, h1);
    *(u32*)(g_x_hi + i + 2) = pkbf(h2, h3);
    *(u32*)(g_x_lo + i)     = pkbf(v.x - h0, v.y - h1);
    *(u32*)(g_x_lo + i + 2) = pkbf(v.z - h2, v.w - h3);
}

// =================================================================
// Prep: transpose W (k-major -> n-major) + split into bf16 hi/lo
// =================================================================
__global__ void wt_split(const float* __restrict__ wq, const float* __restrict__ wk,
                         const float* __restrict__ wv, const float* __restrict__ wo)
{
    __shared__ float tile[32][33];
    const int k0 = blockIdx.x * 32, n0 = blockIdx.y * 32;
    const int mat = n0 >> 10, c0 = n0 & 1023;
    const float* __restrict__ W = (mat == 0) ? wq : (mat == 1) ? wk : (mat == 2) ? wv : wo;
    const int tx = threadIdx.x, ty = threadIdx.y;
#pragma unroll
    for (int i = 0; i < 4; i++)
        tile[ty + i * 8][tx] = W[(size_t)(k0 + ty + i * 8) * 1024 + c0 + tx];
    __syncthreads();
#pragma unroll
    for (int i = 0; i < 4; i++) {
        int rr = ty + i * 8;
        float v = tile[tx][rr];
        float h = bf16rt(v);
        size_t o = (size_t)(n0 + rr) * 1024 + k0 + tx;
        g_wt_hi[o] = __float2bfloat16(h);
        g_wt_lo[o] = __float2bfloat16(v - h);
    }
}

// =================================================================
// HMMA GEMM core (cp.async double-buffered):
// C(128x128 f32) = Ah@Bh^T + Ah@Bl^T + Al@Bh^T
// =================================================================
#define SK 40                       // smem row stride in bf16 (80B)
#define TILE_BYTES  (128 * SK * 2)  // 10240
#define STAGE_BYTES (4 * TILE_BYTES)

__device__ __forceinline__ void gemm_prefetch(
    const __nv_bfloat16* __restrict__ Ah, const __nv_bfloat16* __restrict__ Al,
    const __nv_bfloat16* __restrict__ Bh, const __nv_bfloat16* __restrict__ Bl,
    int m0, int n0row, int k0, u32 st, int row, int half)
{
    const u32 cpo = (u32)(row * SK + half * 16) * 2;
    const size_t ga = (size_t)(m0 + row) * 1024 + k0 + half * 16;
    const size_t gn = (size_t)(n0row + row) * 1024 + k0 + half * 16;
    cpa16(st + cpo,                       Ah + ga);
    cpa16(st + cpo + 16,                  Ah + ga + 8);
    cpa16(st + TILE_BYTES + cpo,          Al + ga);
    cpa16(st + TILE_BYTES + cpo + 16,     Al + ga + 8);
    cpa16(st + 2 * TILE_BYTES + cpo,      Bh + gn);
    cpa16(st + 2 * TILE_BYTES + cpo + 16, Bh + gn + 8);
    cpa16(st + 3 * TILE_BYTES + cpo,      Bl + gn);
    cpa16(st + 3 * TILE_BYTES + cpo + 16, Bl + gn + 8);
    cp_commit();
}

__device__ __forceinline__ void hmma_core(
    const __nv_bfloat16* __restrict__ Ah, const __nv_bfloat16* __restrict__ Al,
    const __nv_bfloat16* __restrict__ Bh, const __nv_bfloat16* __restrict__ Bl,
    int m0, int n0row, __nv_bfloat16* sm, float acc[2][8][4])
{
    const int tid = threadIdx.x;
    const int lane = tid & 31, wid = tid >> 5;
    const int wm = wid >> 1, wn = wid & 1;
    const int lrow = lane & 15, lcol = (lane >> 4) << 3;
    const int row = tid >> 1, half = tid & 1;

    const u32 sb = smem_u32(sm);
    const u32 aoff = (u32)((wm * 32 + lrow) * SK + lcol) * 2;
    const u32 boff = (u32)((wn * 64 + lrow) * SK + lcol) * 2;

    gemm_prefetch(Ah, Al, Bh, Bl, m0, n0row, 0, sb, row, half);

    for (int c = 0; c < 32; ++c) {
        cp_wait0();
        __syncthreads();
        if (c + 1 < 32)
            gemm_prefetch(Ah, Al, Bh, Bl, m0, n0row, (c + 1) * 32,
                          sb + ((c + 1) & 1) * STAGE_BYTES, row, half);

        const u32 st = sb + (c & 1) * STAGE_BYTES;
        const u32 aH = st + aoff, aL = st + TILE_BYTES + aoff;
        const u32 bH = st + 2 * TILE_BYTES + boff, bL = st + 3 * TILE_BYTES + boff;
#pragma unroll
        for (int ks = 0; ks < 2; ++ks) {
            const u32 kofs = ks * 32;
            u32 ah[2][4], al[2][4];
            ldmx4(ah[0], aH + kofs);
            ldmx4(ah[1], aH + 16 * SK * 2 + kofs);
            ldmx4(al[0], aL + kofs);
            ldmx4(al[1], aL + 16 * SK * 2 + kofs);
#pragma unroll
            for (int hf = 0; hf < 2; ++hf) {
                const u32 ho = hf * 32 * SK * 2;
                u32 bh[2][4], bl[2][4];
                ldmx4(bh[0], bH + ho + kofs);
                ldmx4(bh[1], bH + ho + 16 * SK * 2 + kofs);
                ldmx4(bl[0], bL + ho + kofs);
                ldmx4(bl[1], bL + ho + 16 * SK * 2 + kofs);
#pragma unroll
                for (int mi = 0; mi < 2; ++mi)
#pragma unroll
                    for (int jj = 0; jj < 4; ++jj) {
                        const int jb = jj >> 1, s = jj & 1;
                        float* cc = acc[mi][hf * 4 + jj];
                        mma_bf16(cc, ah[mi], bh[jb][s], bh[jb][s + 2]);
                        mma_bf16(cc, ah[mi], bl[jb][s], bl[jb][s + 2]);
                        mma_bf16(cc, al[mi], bh[jb][s], bh[jb][s + 2]);
                    }
            }
        }
    }
}

// =================================================================
// QKV GEMM (HMMA): write q/k/v as bf16 hi/lo [B,H,S,DH]; q scaled
// by 0.125*log2(e) so attention softmax runs in exp2 domain.
// =================================================================
__global__ __launch_bounds__(256, 2) void qkv_hmma()
{
    extern __shared__ __nv_bfloat16 dynsm[];
    const int m0 = blockIdx.x * 128;
    const int n0 = blockIdx.y * 128;          // 0..3071

    float acc[2][8][4] = {};
    hmma_core(g_x_hi, g_x_lo, g_wt_hi, g_wt_lo, m0, n0, dynsm, acc);

    const int tid = threadIdx.x, lane = tid & 31, wid = tid >> 5;
    const int wm = wid >> 1, wn = wid & 1;
    const int gid = lane >> 2, tig = lane & 3;
    const int which = n0 >> 10;
    __nv_bfloat16* __restrict__ oh = (which == 0) ? g_qh : (which == 1) ? g_kh : g_vh;
    __nv_bfloat16* __restrict__ ol = (which == 0) ? g_ql : (which == 1) ? g_kl : g_vl;
    const float sc = (which == 0) ? 0.125f * 1.4426950408889634f : 1.0f;
    const int nl0 = (n0 & 1023) + wn * 64;

#pragma unroll
    for (int mi = 0; mi < 2; ++mi) {
        const int r = m0 + wm * 32 + mi * 16 + gid;
        const int b = r >> 11, s = r & (S_ - 1);
#pragma unroll
        for (int j = 0; j < 8; ++j) {
            const int nl = nl0 + j * 8 + tig * 2;
            const int h = nl >> 6, d = nl & 63;
            const size_t base = ((size_t)(b * H_ + h) * S_ + s) * DH_ + d;
            float v0 = acc[mi][j][0] * sc, v1 = acc[mi][j][1] * sc;
            float v2 = acc[mi][j][2] * sc, v3 = acc[mi][j][3] * sc;
            float h0 = bf16rt(v0), h1 = bf16rt(v1), h2 = bf16rt(v2), h3 = bf16rt(v3);
            *(u32*)(oh + base)           = pkbf(h0, h1);
            *(u32*)(ol + base)           = pkbf(v0 - h0, v1 - h1);
            *(u32*)(oh + base + 8 * DH_) = pkbf(h2, h3);
            *(u32*)(ol + base + 8 * DH_) = pkbf(v2 - h2, v3 - h3);
        }
    }
}

// =================================================================
// Output projection (HMMA) + residual: g_res = ctx @ W_O + x
// =================================================================
__global__ __launch_bounds__(256, 2) void proj_hmma(const float* __restrict__ x)
{
    extern __shared__ __nv_bfloat16 dynsm[];
    const int m0 = blockIdx.x * 128;
    const int n0 = blockIdx.y * 128;          // 0..1023

    float acc[2][8][4] = {};
    hmma_core(g_cx_hi, g_cx_lo, g_wt_hi, g_wt_lo, m0, n0 + 3072, dynsm, acc);

    const int tid = threadIdx.x, lane = tid & 31, wid = tid >> 5;
    const int wm = wid >> 1, wn = wid & 1;
    const int gid = lane >> 2, tig = lane & 3;
    const int nb = n0 + wn * 64;

#pragma unroll
    for (int mi = 0; mi < 2; ++mi) {
        const size_t r = m0 + wm * 32 + mi * 16 + gid;
#pragma unroll
        for (int j = 0; j < 8; ++j) {
            const size_t n = nb + j * 8 + tig * 2;
            float2 x0 = *(const float2*)(x + r * D_ + n);
            float2 x1 = *(const float2*)(x + (r + 8) * D_ + n);
            *(float2*)(g_res + r * D_ + n) =
                make_float2(acc[mi][j][0] + x0.x, acc[mi][j][1] + x0.y);
            *(float2*)(g_res + (r + 8) * D_ + n) =
                make_float2(acc[mi][j][2] + x1.x, acc[mi][j][3] + x1.y);
        }
    }
}

// =================================================================
// Flash attention (HMMA bf16 split, causal, exp2 domain).
// Block = 64 queries / 4 warps; K/V double-buffered via cp.async.
// Dynamic smem: 2 stages x {Kh,Kl,Vh,Vl} (64x64 bf16 each, stride 72).
// Q staged transiently: hi at byte 0 (stage0), lo at byte ASTG (stage1).
// =================================================================
#define SKA 72
#define ATB (64 * SKA * 2)          // 9216 B per tile
#define ASTG (4 * ATB)              // 36864 B per stage

__device__ __forceinline__ void attn_prefetch(size_t gb, int k0t, u32 st,
                                              int row, int half)
{
    const size_t g = gb + (size_t)(k0t + row) * DH_ + half * 32;
    const u32 o = st + (u32)(row * SKA + half * 32) * 2;
#pragma unroll
    for (int i = 0; i < 4; i++) cpa16(o + i * 16,           g_kh + g + i * 8);
#pragma unroll
    for (int i = 0; i < 4; i++) cpa16(o + ATB + i * 16,     g_kl + g + i * 8);
#pragma unroll
    for (int i = 0; i < 4; i++) cpa16(o + 2 * ATB + i * 16, g_vh + g + i * 8);
#pragma unroll
    for (int i = 0; i < 4; i++) cpa16(o + 3 * ATB + i * 16, g_vl + g + i * 8);
    cp_commit();
}

__global__ __launch_bounds__(128, 3) void attn_hmma()
{
    extern __shared__ __nv_bfloat16 asm_[];
    const int tid = threadIdx.x, lane = tid & 31, wm = tid >> 5;
    const int qt = blockIdx.x, bh = blockIdx.y;
    const int q0 = qt * 64;
    const size_t gb = (size_t)bh * S_ * DH_;
    const u32 sb = smem_u32(asm_);
    const int prow = tid >> 1, phalf = tid & 1;

    // ---- stage Q hi (byte 0) / lo (byte ASTG), extract A frags
    {
        const int row = tid >> 1, c = (tid & 1) * 32;
        const uint4* sh = (const uint4*)(g_qh + gb + (size_t)(q0 + row) * DH_ + c);
        const uint4* sl = (const uint4*)(g_ql + gb + (size_t)(q0 + row) * DH_ + c);
        uint4* dh = (uint4*)((char*)asm_ + row * SKA * 2 + c * 2);
        uint4* dl = (uint4*)((char*)asm_ + ASTG + row * SKA * 2 + c * 2);
#pragma unroll
        for (int i = 0; i < 4; i++) { dh[i] = sh[i]; dl[i] = sl[i]; }
    }
    __syncthreads();
    u32 qh[4][4], ql[4][4];
    {
        const u32 off = ((wm * 16 + (lane & 15)) * SKA + (lane >> 4) * 8) * 2;
#pragma unroll
        for (int ks = 0; ks < 4; ks++) {
            ldmx4(qh[ks], sb + off + ks * 32);
            ldmx4(ql[ks], sb + ASTG + off + ks * 32);   // FIX: byte offset ASTG
        }
    }
    __syncthreads();

    attn_prefetch(gb, 0, sb, prow, phalf);

    float o[8][4] = {};
    float mA = -1e30f, mB = -1e30f, lA = 0.f, lB = 0.f;
    const int rowA = q0 + wm * 16 + (lane >> 2);
    const u32 sboff = ((lane & 15) * SKA + (lane >> 4) * 8) * 2;
    const u32 vtoff = ((((lane >> 3) & 1) * 8 + (lane & 7)) * SKA + (lane >> 4) * 8) * 2;

    for (int kt = 0; kt <= qt; ++kt) {
        const int k0t = kt * 64;
        cp_wait0();
        __syncthreads();
        if (kt < qt)
            attn_prefetch(gb, (kt + 1) * 64, sb + ((kt + 1) & 1) * ASTG, prow, phalf);

        const u32 st = sb + (kt & 1) * ASTG;
        const u32 kh_b = st + sboff,            kl_b = st + ATB + sboff;
        const u32 vh_b = st + 2 * ATB + vtoff,  vl_b = st + 3 * ATB + vtoff;

        if (k0t <= q0 + wm * 16 + 15) {   // warp-uniform: skip fully-masked tiles
            // ---- S = Q K^T (3-term split), f32 accum
            float s[8][4] = {};
#pragma unroll
            for (int ks = 0; ks < 4; ks++)
#pragma unroll
                for (int g = 0; g < 4; g++) {
                    u32 kh4[4], kl4[4];
                    ldmx4(kh4, kh_b + g * 16 * SKA * 2 + ks * 32);
                    ldmx4(kl4, kl_b + g * 16 * SKA * 2 + ks * 32);
                    mma_bf16(s[2 * g],     qh[ks], kh4[0], kh4[2]);
                    mma_bf16(s[2 * g],     qh[ks], kl4[0], kl4[2]);
                    mma_bf16(s[2 * g],     ql[ks], kh4[0], kh4[2]);
                    mma_bf16(s[2 * g + 1], qh[ks], kh4[1], kh4[3]);
                    mma_bf16(s[2 * g + 1], qh[ks], kl4[1], kl4[3]);
                    mma_bf16(s[2 * g + 1], ql[ks], kh4[1], kh4[3]);
                }

            // ---- causal mask (diagonal tiles only)
            if (k0t + 63 > q0 + wm * 16) {
#pragma unroll
                for (int b = 0; b < 8; b++) {
                    int cb = k0t + b * 8 + (lane & 3) * 2;
                    if (cb > rowA)         s[b][0] = -1e30f;
                    if (cb + 1 > rowA)     s[b][1] = -1e30f;
                    if (cb > rowA + 8)     s[b][2] = -1e30f;
                    if (cb + 1 > rowA + 8) s[b][3] = -1e30f;
                }
            }

            // ---- online softmax (exp2 domain; quad lanes share a row)
            float nmA = mA, nmB = mB;
#pragma unroll
            for (int b = 0; b < 8; b++) {
                nmA = fmaxf(nmA, fmaxf(s[b][0], s[b][1]));
                nmB = fmaxf(nmB, fmaxf(s[b][2], s[b][3]));
            }
            nmA = fmaxf(nmA, __shfl_xor_sync(~0u, nmA, 1));
            nmA = fmaxf(nmA, __shfl_xor_sync(~0u, nmA, 2));
            nmB = fmaxf(nmB, __shfl_xor_sync(~0u, nmB, 1));
            nmB = fmaxf(nmB, __shfl_xor_sync(~0u, nmB, 2));
            float alA = ex2f(mA - nmA), alB = ex2f(mB - nmB);
            mA = nmA; mB = nmB;
#pragma unroll
            for (int b = 0; b < 8; b++) {
                o[b][0] *= alA; o[b][1] *= alA;
                o[b][2] *= alB; o[b][3] *= alB;
            }

            // ---- P = exp2(S-m), split hi/lo, PV (3-term) per kstep
            float sumA = 0.f, sumB = 0.f;
#pragma unroll
            for (int ks = 0; ks < 4; ks++) {
                float p[8];
                p[0] = ex2f(s[2 * ks][0] - mA);     p[1] = ex2f(s[2 * ks][1] - mA);
                p[2] = ex2f(s[2 * ks][2] - mB);     p[3] = ex2f(s[2 * ks][3] - mB);
                p[4] = ex2f(s[2 * ks + 1][0] - mA); p[5] = ex2f(s[2 * ks + 1][1] - mA);
                p[6] = ex2f(s[2 * ks + 1][2] - mB); p[7] = ex2f(s[2 * ks + 1][3] - mB);
                sumA += p[0] + p[1] + p[4] + p[5];
                sumB += p[2] + p[3] + p[6] + p[7];
                float hf[8];
#pragma unroll
                for (int e = 0; e < 8; e++) hf[e] = bf16rt(p[e]);
                u32 ph4[4], pl4[4];
                ph4[0] = pkbf(hf[0], hf[1]); ph4[1] = pkbf(hf[2], hf[3]);
                ph4[2] = pkbf(hf[4], hf[5]); ph4[3] = pkbf(hf[6], hf[7]);
                pl4[0] = pkbf(p[0] - hf[0], p[1] - hf[1]);
                pl4[1] = pkbf(p[2] - hf[2], p[3] - hf[3]);
                pl4[2] = pkbf(p[4] - hf[4], p[5] - hf[5]);
                pl4[3] = pkbf(p[6] - hf[6], p[7] - hf[7]);
#pragma unroll
                for (int g = 0; g < 4; g++) {
                    u32 vh4[4], vl4[4];
                    ldmx4t(vh4, vh_b + ks * 16 * SKA * 2 + g * 32);
                    ldmx4t(vl4, vl_b + ks * 16 * SKA * 2 + g * 32);
                    mma_bf16(o[2 * g],     ph4, vh4[0], vh4[1]);
                    mma_bf16(o[2 * g],     ph4, vl4[0], vl4[1]);
                    mma_bf16(o[2 * g],     pl4, vh4[0], vh4[1]);
                    mma_bf16(o[2 * g + 1], ph4, vh4[2], vh4[3]);
                    mma_bf16(o[2 * g + 1], ph4, vl4[2], vl4[3]);
                    mma_bf16(o[2 * g + 1], pl4, vh4[2], vh4[3]);
                }
            }
            sumA += __shfl_xor_sync(~0u, sumA, 1);
            sumA += __shfl_xor_sync(~0u, sumA, 2);
            sumB += __shfl_xor_sync(~0u, sumB, 1);
            sumB += __shfl_xor_sync(~0u, sumB, 2);
            lA = lA * alA + sumA;
            lB = lB * alB + sumB;
        }
    }

    // ---- write ctx as bf16 hi/lo [m][1024] for proj GEMM
    const float iA = 1.0f / lA, iB = 1.0f / lB;
    const int bb = bh >> 4, hh = bh & 15;
    const size_t m0r = (size_t)(bb * S_ + rowA) * D_ + hh * 64;
    const size_t m1r = m0r + 8 * D_;
#pragma unroll
    for (int b = 0; b < 8; b++) {
        int col = b * 8 + (lane & 3) * 2;
        float f0 = o[b][0] * iA, f1 = o[b][1] * iA;
        float f2 = o[b][2] * iB, f3 = o[b][3] * iB;
        float h0 = bf16rt(f0), h1 = bf16rt(f1), h2 = bf16rt(f2), h3 = bf16rt(f3);
        *(u32*)(g_cx_hi + m0r + col) = pkbf(h0, h1);
        *(u32*)(g_cx_lo + m0r + col) = pkbf(f0 - h0, f1 - h1);
        *(u32*)(g_cx_hi + m1r + col) = pkbf(h2, h3);
        *(u32*)(g_cx_lo + m1r + col) = pkbf(f2 - h2, f3 - h3);
    }
}

// =================================================================
// LayerNorm over last dim (1024)
// =================================================================
__global__ __launch_bounds__(256) void ln_kernel(
    const float* __restrict__ gamma,
    const float* __restrict__ beta,
    float* __restrict__ out)
{
    __shared__ float ws[8], wq2[8];
    const int row = blockIdx.x;
    const int t = threadIdx.x;
    const int lane = t & 31, w = t >> 5;
    const float* rp = g_res + (size_t)row * D_;

    float4 v = *(const float4*)(rp + t * 4);
    float s = v.x + v.y + v.z + v.w;
    float q = v.x * v.x + v.y * v.y + v.z * v.z + v.w * v.w;
#pragma unroll
    for (int o = 16; o > 0; o >>= 1) {
        s += __shfl_xor_sync(0xffffffffu, s, o);
        q += __shfl_xor_sync(0xffffffffu, q, o);
    }
    if (lane == 0) { ws[w] = s; wq2[w] = q; }
    __syncthreads();
    float S = 0.f, Q = 0.f;
#pragma unroll
    for (int i = 0; i < 8; i++) { S += ws[i]; Q += wq2[i]; }

    float mu  = S * (1.0f / 1024.0f);
    float var = Q * (1.0f / 1024.0f) - mu * mu;
    float rstd = rsqrtf(var + 1e-5f);

    float4 g  = *(const float4*)(gamma + t * 4);
    float4 bt = *(const float4*)(beta  + t * 4);
    float4 o4;
    o4.x = (v.x - mu) * rstd * g.x + bt.x;
    o4.y = (v.y - mu) * rstd * g.y + bt.y;
    o4.z = (v.z - mu) * rstd * g.z + bt.z;
    o4.w = (v.w - mu) * rstd * g.w + bt.w;
    *(float4*)(out + (size_t)row * D_ + t * 4) = o4;
}

// =================================================================
extern "C" void kernel_launch(void* const* d_in, const int* in_sizes, int n_in,
                              void* d_out, int out_size)
{
    const float* x     = (const float*)d_in[0];
    const float* wq    = (const float*)d_in[1];
    const float* wk    = (const float*)d_in[2];
    const float* wv    = (const float*)d_in[3];
    const float* wo    = (const float*)d_in[4];
    const float* gamma = (const float*)d_in[5];
    const float* beta  = (const float*)d_in[6];
    float* out = (float*)d_out;

    const int gemm_smem = 2 * STAGE_BYTES;   // 80 KB double-buffered
    const int attn_smem = 2 * ASTG;          // 72 KB double-buffered
    cudaFuncSetAttribute(qkv_hmma,
                         cudaFuncAttributeMaxDynamicSharedMemorySize, gemm_smem);
    cudaFuncSetAttribute(proj_hmma,
                         cudaFuncAttributeMaxDynamicSharedMemorySize, gemm_smem);
    cudaFuncSetAttribute(attn_hmma,
                         cudaFuncAttributeMaxDynamicSharedMemorySize, attn_smem);

    split_x<<<M_, 256>>>(x);
    wt_split<<<dim3(32, 128), dim3(32, 8)>>>(wq, wk, wv, wo);
    qkv_hmma<<<dim3(M_ / 128, 3072 / 128), 256, gemm_smem>>>();
    attn_hmma<<<dim3(S_ / 64, B_ * H_), 128, attn_smem>>>();
    proj_hmma<<<dim3(M_ / 128, D_ / 128), 256, gemm_smem>>>(x);
    ln_kernel<<<M_, 256>>>(gamma, beta, out);
}

// round 15
// speedup vs baseline: 2.3586x; 2.3586x over previous
#include <cuda_runtime.h>
#include <cuda_fp16.h>
#include <math.h>

#define B_  4
#define S_  2048
#define D_  1024
#define H_  16
#define DH_ 64
#define M_  (B_*S_)          // 8192 rows

typedef unsigned long long u64;
typedef unsigned int u32;

// ---------------- helpers ----------------------------------------
__device__ __forceinline__ u32 smem_u32(const void* p) {
    u32 a;
    asm("{ .reg .u64 t; cvta.to.shared.u64 t, %1; cvt.u32.u64 %0, t; }"
        : "=r"(a) : "l"(p));
    return a;
}
__device__ __forceinline__ void ldmx4(u32* r, u32 addr) {
    asm volatile("ldmatrix.sync.aligned.m8n8.x4.shared.b16 {%0,%1,%2,%3}, [%4];"
                 : "=r"(r[0]), "=r"(r[1]), "=r"(r[2]), "=r"(r[3]) : "r"(addr));
}
__device__ __forceinline__ void ldmx4t(u32* r, u32 addr) {
    asm volatile("ldmatrix.sync.aligned.m8n8.x4.trans.shared.b16 {%0,%1,%2,%3}, [%4];"
                 : "=r"(r[0]), "=r"(r[1]), "=r"(r[2]), "=r"(r[3]) : "r"(addr));
}
__device__ __forceinline__ void mma_f16(float* c, const u32* a, u32 b0, u32 b1) {
    asm volatile(
        "mma.sync.aligned.m16n8k16.row.col.f32.f16.f16.f32 "
        "{%0,%1,%2,%3}, {%4,%5,%6,%7}, {%8,%9}, {%0,%1,%2,%3};"
        : "+f"(c[0]), "+f"(c[1]), "+f"(c[2]), "+f"(c[3])
        : "r"(a[0]), "r"(a[1]), "r"(a[2]), "r"(a[3]), "r"(b0), "r"(b1));
}
// pack two floats -> f16x2 {lo, hi}
__device__ __forceinline__ u32 pkhf(float lo, float hi) {
    u32 r; asm("cvt.rn.f16x2.f32 %0, %2, %1;" : "=r"(r) : "f"(lo), "f"(hi)); return r;
}
__device__ __forceinline__ float ex2f(float x) {
    float y; asm("ex2.approx.ftz.f32 %0, %1;" : "=f"(y) : "f"(x)); return y;
}
__device__ __forceinline__ void cpa16(u32 dst, const void* src) {
    asm volatile("cp.async.cg.shared.global [%0], [%1], 16;"
                 :: "r"(dst), "l"(__cvta_generic_to_global(src)) : "memory");
}
__device__ __forceinline__ void cp_commit() {
    asm volatile("cp.async.commit_group;" ::: "memory");
}
__device__ __forceinline__ void cp_wait0() {
    asm volatile("cp.async.wait_group 0;" ::: "memory");
}

// ---------------- scratch (no allocations allowed) ----------------
__device__ float g_res[(size_t)M_*D_];           // pre-layernorm
__device__ __half g_x [(size_t)M_*D_];           // x in fp16
__device__ __half g_wt[(size_t)4096*1024];       // [n][k]: 0-3071 WQKV^T, 3072-4095 WO^T
__device__ __half g_q [(size_t)B_*H_*S_*DH_];    // [B,H,S,DH], q pre-scaled 0.125*log2e
__device__ __half g_k [(size_t)B_*H_*S_*DH_];
__device__ __half g_v [(size_t)B_*H_*S_*DH_];
__device__ __half g_cx[(size_t)M_*D_];           // ctx [m][k] fp16

// =================================================================
// Prep: convert x to fp16
// =================================================================
__global__ __launch_bounds__(256) void cvt_x(const float* __restrict__ x)
{
    size_t i = (size_t)blockIdx.x * 1024 + threadIdx.x * 4;
    float4 v = *(const float4*)(x + i);
    *(u32*)(g_x + i)     = pkhf(v.x, v.y);
    *(u32*)(g_x + i + 2) = pkhf(v.z, v.w);
}

// =================================================================
// Prep: transpose W (k-major -> n-major) to fp16
// =================================================================
__global__ void wt_t(const float* __restrict__ wq, const float* __restrict__ wk,
                     const float* __restrict__ wv, const float* __restrict__ wo)
{
    __shared__ float tile[32][33];
    const int k0 = blockIdx.x * 32, n0 = blockIdx.y * 32;
    const int mat = n0 >> 10, c0 = n0 & 1023;
    const float* __restrict__ W = (mat == 0) ? wq : (mat == 1) ? wk : (mat == 2) ? wv : wo;
    const int tx = threadIdx.x, ty = threadIdx.y;
#pragma unroll
    for (int i = 0; i < 4; i++)
        tile[ty + i * 8][tx] = W[(size_t)(k0 + ty + i * 8) * 1024 + c0 + tx];
    __syncthreads();
#pragma unroll
    for (int i = 0; i < 4; i++) {
        int rr = ty + i * 8;
        g_wt[(size_t)(n0 + rr) * 1024 + k0 + tx] = __float2half(tile[tx][rr]);
    }
}

// =================================================================
// HMMA GEMM core (fp16 single-term, cp.async double-buffered):
// C(128x128 f32) = A @ B^T ; A [m][k], B [n][k], both fp16.
// =================================================================
#define SK 40                       // smem row stride in fp16 (80B)
#define TILE_BYTES  (128 * SK * 2)  // 10240
#define STAGE_BYTES (2 * TILE_BYTES)

__device__ __forceinline__ void gemm_prefetch(
    const __half* __restrict__ A, const __half* __restrict__ B,
    int m0, int n0row, int k0, u32 st, int row, int half)
{
    const u32 cpo = (u32)(row * SK + half * 16) * 2;
    const size_t ga = (size_t)(m0 + row) * 1024 + k0 + half * 16;
    const size_t gn = (size_t)(n0row + row) * 1024 + k0 + half * 16;
    cpa16(st + cpo,                   A + ga);
    cpa16(st + cpo + 16,              A + ga + 8);
    cpa16(st + TILE_BYTES + cpo,      B + gn);
    cpa16(st + TILE_BYTES + cpo + 16, B + gn + 8);
    cp_commit();
}

__device__ __forceinline__ void hmma_core(
    const __half* __restrict__ A, const __half* __restrict__ B,
    int m0, int n0row, __half* sm, float acc[2][8][4])
{
    const int tid = threadIdx.x;
    const int lane = tid & 31, wid = tid >> 5;
    const int wm = wid >> 1, wn = wid & 1;
    const int lrow = lane & 15, lcol = (lane >> 4) << 3;
    const int row = tid >> 1, half = tid & 1;

    const u32 sb = smem_u32(sm);
    const u32 aoff = (u32)((wm * 32 + lrow) * SK + lcol) * 2;
    const u32 boff = (u32)((wn * 64 + lrow) * SK + lcol) * 2;

    gemm_prefetch(A, B, m0, n0row, 0, sb, row, half);

    for (int c = 0; c < 32; ++c) {
        cp_wait0();
        __syncthreads();
        if (c + 1 < 32)
            gemm_prefetch(A, B, m0, n0row, (c + 1) * 32,
                          sb + ((c + 1) & 1) * STAGE_BYTES, row, half);

        const u32 st = sb + (c & 1) * STAGE_BYTES;
        const u32 aB = st + aoff, bB = st + TILE_BYTES + boff;
#pragma unroll
        for (int ks = 0; ks < 2; ++ks) {
            const u32 kofs = ks * 32;
            u32 a2[2][4];
            ldmx4(a2[0], aB + kofs);
            ldmx4(a2[1], aB + 16 * SK * 2 + kofs);
#pragma unroll
            for (int hf = 0; hf < 2; ++hf) {
                const u32 ho = hf * 32 * SK * 2;
                u32 b2[2][4];
                ldmx4(b2[0], bB + ho + kofs);
                ldmx4(b2[1], bB + ho + 16 * SK * 2 + kofs);
#pragma unroll
                for (int mi = 0; mi < 2; ++mi)
#pragma unroll
                    for (int jj = 0; jj < 4; ++jj) {
                        const int jb = jj >> 1, sl = jj & 1;
                        mma_f16(acc[mi][hf * 4 + jj], a2[mi],
                                b2[jb][sl], b2[jb][sl + 2]);
                    }
            }
        }
    }
}

// =================================================================
// QKV GEMM: write q/k/v fp16 [B,H,S,DH]; q scaled 0.125*log2(e)
// =================================================================
__global__ __launch_bounds__(256, 2) void qkv_hmma()
{
    extern __shared__ __half dynsm[];
    const int m0 = blockIdx.x * 128;
    const int n0 = blockIdx.y * 128;          // 0..3071

    float acc[2][8][4] = {};
    hmma_core(g_x, g_wt, m0, n0, dynsm, acc);

    const int tid = threadIdx.x, lane = tid & 31, wid = tid >> 5;
    const int wm = wid >> 1, wn = wid & 1;
    const int gid = lane >> 2, tig = lane & 3;
    const int which = n0 >> 10;
    __half* __restrict__ op = (which == 0) ? g_q : (which == 1) ? g_k : g_v;
    const float sc = (which == 0) ? 0.125f * 1.4426950408889634f : 1.0f;
    const int nl0 = (n0 & 1023) + wn * 64;

#pragma unroll
    for (int mi = 0; mi < 2; ++mi) {
        const int r = m0 + wm * 32 + mi * 16 + gid;
        const int b = r >> 11, s = r & (S_ - 1);
#pragma unroll
        for (int j = 0; j < 8; ++j) {
            const int nl = nl0 + j * 8 + tig * 2;
            const int h = nl >> 6, d = nl & 63;
            const size_t base = ((size_t)(b * H_ + h) * S_ + s) * DH_ + d;
            *(u32*)(op + base)           = pkhf(acc[mi][j][0] * sc, acc[mi][j][1] * sc);
            *(u32*)(op + base + 8 * DH_) = pkhf(acc[mi][j][2] * sc, acc[mi][j][3] * sc);
        }
    }
}

// =================================================================
// Output projection + residual: g_res = ctx @ W_O + x
// =================================================================
__global__ __launch_bounds__(256, 2) void proj_hmma(const float* __restrict__ x)
{
    extern __shared__ __half dynsm[];
    const int m0 = blockIdx.x * 128;
    const int n0 = blockIdx.y * 128;          // 0..1023

    float acc[2][8][4] = {};
    hmma_core(g_cx, g_wt, m0, n0 + 3072, dynsm, acc);

    const int tid = threadIdx.x, lane = tid & 31, wid = tid >> 5;
    const int wm = wid >> 1, wn = wid & 1;
    const int gid = lane >> 2, tig = lane & 3;
    const int nb = n0 + wn * 64;

#pragma unroll
    for (int mi = 0; mi < 2; ++mi) {
        const size_t r = m0 + wm * 32 + mi * 16 + gid;
#pragma unroll
        for (int j = 0; j < 8; ++j) {
            const size_t n = nb + j * 8 + tig * 2;
            float2 x0 = *(const float2*)(x + r * D_ + n);
            float2 x1 = *(const float2*)(x + (r + 8) * D_ + n);
            *(float2*)(g_res + r * D_ + n) =
                make_float2(acc[mi][j][0] + x0.x, acc[mi][j][1] + x0.y);
            *(float2*)(g_res + (r + 8) * D_ + n) =
                make_float2(acc[mi][j][2] + x1.x, acc[mi][j][3] + x1.y);
        }
    }
}

// =================================================================
// Flash attention (fp16 HMMA, causal, exp2 domain).
// Block = 64 queries / 4 warps; static smem, plain loads (R9 style).
// =================================================================
#define SKA 72

__global__ __launch_bounds__(128, 4) void attn_hmma()
{
    __shared__ __align__(16) __half smK[64 * SKA];
    __shared__ __align__(16) __half smV[64 * SKA];

    const int tid = threadIdx.x, lane = tid & 31, wm = tid >> 5;
    const int qt = blockIdx.x, bh = blockIdx.y;
    const int q0 = qt * 64;
    const size_t gb = (size_t)bh * S_ * DH_;
    const u32 sbK = smem_u32(smK), sbV = smem_u32(smV);

    // ---- stage Q (fp16) into smK, extract per-warp A fragments
    {
        const int row = tid >> 1, c = (tid & 1) * 32;
        const uint4* s = (const uint4*)(g_q + gb + (size_t)(q0 + row) * DH_ + c);
        uint4* d = (uint4*)(smK + row * SKA + c);
#pragma unroll
        for (int i = 0; i < 4; i++) d[i] = s[i];
    }
    __syncthreads();
    u32 qf[4][4];
    {
        const u32 off = ((wm * 16 + (lane & 15)) * SKA + (lane >> 4) * 8) * 2;
#pragma unroll
        for (int ks = 0; ks < 4; ks++)
            ldmx4(qf[ks], sbK + off + ks * 32);
    }
    __syncthreads();

    float o[8][4] = {};
    float mA = -1e30f, mB = -1e30f, lA = 0.f, lB = 0.f;
    const int rowA = q0 + wm * 16 + (lane >> 2);
    const u32 sboff = ((lane & 15) * SKA + (lane >> 4) * 8) * 2;
    const u32 vtoff = ((((lane >> 3) & 1) * 8 + (lane & 7)) * SKA + (lane >> 4) * 8) * 2;

    for (int kt = 0; kt <= qt; ++kt) {
        const int k0t = kt * 64;
        {   // load K/V tiles (64x64 fp16 each), 128 threads
            const int row = tid >> 1, c = (tid & 1) * 32;
            const size_t g = gb + (size_t)(k0t + row) * DH_ + c;
            const uint4* s0 = (const uint4*)(g_k + g);
            const uint4* s1 = (const uint4*)(g_v + g);
            uint4* d0 = (uint4*)(smK + row * SKA + c);
            uint4* d1 = (uint4*)(smV + row * SKA + c);
#pragma unroll
            for (int i = 0; i < 4; i++) { d0[i] = s0[i]; d1[i] = s1[i]; }
        }
        __syncthreads();

        if (k0t <= q0 + wm * 16 + 15) {   // warp-uniform: skip fully-masked tiles
            // ---- S = Q K^T, f32 accum
            float s[8][4] = {};
#pragma unroll
            for (int ks = 0; ks < 4; ks++)
#pragma unroll
                for (int g = 0; g < 4; g++) {
                    u32 k4[4];
                    ldmx4(k4, sbK + sboff + g * 16 * SKA * 2 + ks * 32);
                    mma_f16(s[2 * g],     qf[ks], k4[0], k4[2]);
                    mma_f16(s[2 * g + 1], qf[ks], k4[1], k4[3]);
                }

            // ---- causal mask (diagonal tiles only)
            if (k0t + 63 > q0 + wm * 16) {
#pragma unroll
                for (int b = 0; b < 8; b++) {
                    int cb = k0t + b * 8 + (lane & 3) * 2;
                    if (cb > rowA)         s[b][0] = -1e30f;
                    if (cb + 1 > rowA)     s[b][1] = -1e30f;
                    if (cb > rowA + 8)     s[b][2] = -1e30f;
                    if (cb + 1 > rowA + 8) s[b][3] = -1e30f;
                }
            }

            // ---- online softmax (exp2 domain; quad lanes share a row)
            float nmA = mA, nmB = mB;
#pragma unroll
            for (int b = 0; b < 8; b++) {
                nmA = fmaxf(nmA, fmaxf(s[b][0], s[b][1]));
                nmB = fmaxf(nmB, fmaxf(s[b][2], s[b][3]));
            }
            nmA = fmaxf(nmA, __shfl_xor_sync(~0u, nmA, 1));
            nmA = fmaxf(nmA, __shfl_xor_sync(~0u, nmA, 2));
            nmB = fmaxf(nmB, __shfl_xor_sync(~0u, nmB, 1));
            nmB = fmaxf(nmB, __shfl_xor_sync(~0u, nmB, 2));
            float alA = ex2f(mA - nmA), alB = ex2f(mB - nmB);
            mA = nmA; mB = nmB;
#pragma unroll
            for (int b = 0; b < 8; b++) {
                o[b][0] *= alA; o[b][1] *= alA;
                o[b][2] *= alB; o[b][3] *= alB;
            }

            // ---- P = exp2(S-m) fp16, PV per kstep
            float sumA = 0.f, sumB = 0.f;
#pragma unroll
            for (int ks = 0; ks < 4; ks++) {
                float p[8];
                p[0] = ex2f(s[2 * ks][0] - mA);     p[1] = ex2f(s[2 * ks][1] - mA);
                p[2] = ex2f(s[2 * ks][2] - mB);     p[3] = ex2f(s[2 * ks][3] - mB);
                p[4] = ex2f(s[2 * ks + 1][0] - mA); p[5] = ex2f(s[2 * ks + 1][1] - mA);
                p[6] = ex2f(s[2 * ks + 1][2] - mB); p[7] = ex2f(s[2 * ks + 1][3] - mB);
                sumA += p[0] + p[1] + p[4] + p[5];
                sumB += p[2] + p[3] + p[6] + p[7];
                u32 ph4[4];
                ph4[0] = pkhf(p[0], p[1]); ph4[1] = pkhf(p[2], p[3]);
                ph4[2] = pkhf(p[4], p[5]); ph4[3] = pkhf(p[6], p[7]);
#pragma unroll
                for (int g = 0; g < 4; g++) {
                    u32 v4[4];
                    ldmx4t(v4, sbV + vtoff + ks * 16 * SKA * 2 + g * 32);
                    mma_f16(o[2 * g],     ph4, v4[0], v4[1]);
                    mma_f16(o[2 * g + 1], ph4, v4[2], v4[3]);
                }
            }
            sumA += __shfl_xor_sync(~0u, sumA, 1);
            sumA += __shfl_xor_sync(~0u, sumA, 2);
            sumB += __shfl_xor_sync(~0u, sumB, 1);
            sumB += __shfl_xor_sync(~0u, sumB, 2);
            lA = lA * alA + sumA;
            lB = lB * alB + sumB;
        }
        __syncthreads();
    }

    // ---- write ctx fp16 [m][1024] for proj GEMM
    const float iA = 1.0f / lA, iB = 1.0f / lB;
    const int bb = bh >> 4, hh = bh & 15;
    const size_t m0r = (size_t)(bb * S_ + rowA) * D_ + hh * 64;
    const size_t m1r = m0r + 8 * D_;
#pragma unroll
    for (int b = 0; b < 8; b++) {
        int col = b * 8 + (lane & 3) * 2;
        *(u32*)(g_cx + m0r + col) = pkhf(o[b][0] * iA, o[b][1] * iA);
        *(u32*)(g_cx + m1r + col) = pkhf(o[b][2] * iB, o[b][3] * iB);
    }
}

// =================================================================
// LayerNorm over last dim (1024)
// =================================================================
__global__ __launch_bounds__(256) void ln_kernel(
    const float* __restrict__ gamma,
    const float* __restrict__ beta,
    float* __restrict__ out)
{
    __shared__ float ws[8], wq2[8];
    const int row = blockIdx.x;
    const int t = threadIdx.x;
    const int lane = t & 31, w = t >> 5;
    const float* rp = g_res + (size_t)row * D_;

    float4 v = *(const float4*)(rp + t * 4);
    float s = v.x + v.y + v.z + v.w;
    float q = v.x * v.x + v.y * v.y + v.z * v.z + v.w * v.w;
#pragma unroll
    for (int o = 16; o > 0; o >>= 1) {
        s += __shfl_xor_sync(0xffffffffu, s, o);
        q += __shfl_xor_sync(0xffffffffu, q, o);
    }
    if (lane == 0) { ws[w] = s; wq2[w] = q; }
    __syncthreads();
    float S = 0.f, Q = 0.f;
#pragma unroll
    for (int i = 0; i < 8; i++) { S += ws[i]; Q += wq2[i]; }

    float mu  = S * (1.0f / 1024.0f);
    float var = Q * (1.0f / 1024.0f) - mu * mu;
    float rstd = rsqrtf(var + 1e-5f);

    float4 g  = *(const float4*)(gamma + t * 4);
    float4 bt = *(const float4*)(beta  + t * 4);
    float4 o4;
    o4.x = (v.x - mu) * rstd * g.x + bt.x;
    o4.y = (v.y - mu) * rstd * g.y + bt.y;
    o4.z = (v.z - mu) * rstd * g.z + bt.z;
    o4.w = (v.w - mu) * rstd * g.w + bt.w;
    *(float4*)(out + (size_t)row * D_ + t * 4) = o4;
}

// =================================================================
extern "C" void kernel_launch(void* const* d_in, const int* in_sizes, int n_in,
                              void* d_out, int out_size)
{
    const float* x     = (const float*)d_in[0];
    const float* wq    = (const float*)d_in[1];
    const float* wk    = (const float*)d_in[2];
    const float* wv    = (const float*)d_in[3];
    const float* wo    = (const float*)d_in[4];
    const float* gamma = (const float*)d_in[5];
    const float* beta  = (const float*)d_in[6];
    float* out = (float*)d_out;

    const int gemm_smem = 2 * STAGE_BYTES;   // 40 KB double-buffered
    cudaFuncSetAttribute(qkv_hmma,
                         cudaFuncAttributeMaxDynamicSharedMemorySize, gemm_smem);
    cudaFuncSetAttribute(proj_hmma,
                         cudaFuncAttributeMaxDynamicSharedMemorySize, gemm_smem);

    cvt_x<<<M_, 256>>>(x);
    wt_t<<<dim3(32, 128), dim3(32, 8)>>>(wq, wk, wv, wo);
    qkv_hmma<<<dim3(M_ / 128, 3072 / 128), 256, gemm_smem>>>();
    attn_hmma<<<dim3(S_ / 64, B_ * H_), 128>>>();
    proj_hmma<<<dim3(M_ / 128, D_ / 128), 256, gemm_smem>>>(x);
    ln_kernel<<<M_, 256>>>(gamma, beta, out);
}

// round 16
// speedup vs baseline: 2.3968x; 1.0162x over previous
#include <cuda_runtime.h>
#include <cuda_fp16.h>
#include <math.h>

#define B_  4
#define S_  2048
#define D_  1024
#define H_  16
#define DH_ 64
#define M_  (B_*S_)          // 8192 rows

typedef unsigned long long u64;
typedef unsigned int u32;

// ---------------- helpers ----------------------------------------
__device__ __forceinline__ u32 smem_u32(const void* p) {
    u32 a;
    asm("{ .reg .u64 t; cvta.to.shared.u64 t, %1; cvt.u32.u64 %0, t; }"
        : "=r"(a) : "l"(p));
    return a;
}
__device__ __forceinline__ void ldmx4(u32* r, u32 addr) {
    asm volatile("ldmatrix.sync.aligned.m8n8.x4.shared.b16 {%0,%1,%2,%3}, [%4];"
                 : "=r"(r[0]), "=r"(r[1]), "=r"(r[2]), "=r"(r[3]) : "r"(addr));
}
__device__ __forceinline__ void ldmx4t(u32* r, u32 addr) {
    asm volatile("ldmatrix.sync.aligned.m8n8.x4.trans.shared.b16 {%0,%1,%2,%3}, [%4];"
                 : "=r"(r[0]), "=r"(r[1]), "=r"(r[2]), "=r"(r[3]) : "r"(addr));
}
__device__ __forceinline__ void mma_f16(float* c, const u32* a, u32 b0, u32 b1) {
    asm volatile(
        "mma.sync.aligned.m16n8k16.row.col.f32.f16.f16.f32 "
        "{%0,%1,%2,%3}, {%4,%5,%6,%7}, {%8,%9}, {%0,%1,%2,%3};"
        : "+f"(c[0]), "+f"(c[1]), "+f"(c[2]), "+f"(c[3])
        : "r"(a[0]), "r"(a[1]), "r"(a[2]), "r"(a[3]), "r"(b0), "r"(b1));
}
// pack two floats -> f16x2 {lo, hi}
__device__ __forceinline__ u32 pkhf(float lo, float hi) {
    u32 r; asm("cvt.rn.f16x2.f32 %0, %2, %1;" : "=r"(r) : "f"(lo), "f"(hi)); return r;
}
__device__ __forceinline__ float ex2f(float x) {
    float y; asm("ex2.approx.ftz.f32 %0, %1;" : "=f"(y) : "f"(x)); return y;
}
__device__ __forceinline__ void cpa16(u32 dst, const void* src) {
    asm volatile("cp.async.cg.shared.global [%0], [%1], 16;"
                 :: "r"(dst), "l"(__cvta_generic_to_global(src)) : "memory");
}
__device__ __forceinline__ void cp_commit() {
    asm volatile("cp.async.commit_group;" ::: "memory");
}
__device__ __forceinline__ void cp_wait0() {
    asm volatile("cp.async.wait_group 0;" ::: "memory");
}

// ---------------- scratch (no allocations allowed) ----------------
__device__ float g_res[(size_t)M_*D_];           // pre-layernorm
__device__ __half g_x [(size_t)M_*D_];           // x in fp16
__device__ __half g_wt[(size_t)4096*1024];       // [n][k]: 0-3071 WQKV^T, 3072-4095 WO^T
__device__ __half g_q [(size_t)B_*H_*S_*DH_];    // [B,H,S,DH], q pre-scaled 0.125*log2e
__device__ __half g_k [(size_t)B_*H_*S_*DH_];
__device__ __half g_v [(size_t)B_*H_*S_*DH_];
__device__ __half g_cx[(size_t)M_*D_];           // ctx [m][k] fp16

// =================================================================
// Prep: convert x to fp16
// =================================================================
__global__ __launch_bounds__(256) void cvt_x(const float* __restrict__ x)
{
    size_t i = (size_t)blockIdx.x * 1024 + threadIdx.x * 4;
    float4 v = *(const float4*)(x + i);
    *(u32*)(g_x + i)     = pkhf(v.x, v.y);
    *(u32*)(g_x + i + 2) = pkhf(v.z, v.w);
}

// =================================================================
// Prep: transpose W (k-major -> n-major) to fp16
// =================================================================
__global__ void wt_t(const float* __restrict__ wq, const float* __restrict__ wk,
                     const float* __restrict__ wv, const float* __restrict__ wo)
{
    __shared__ float tile[32][33];
    const int k0 = blockIdx.x * 32, n0 = blockIdx.y * 32;
    const int mat = n0 >> 10, c0 = n0 & 1023;
    const float* __restrict__ W = (mat == 0) ? wq : (mat == 1) ? wk : (mat == 2) ? wv : wo;
    const int tx = threadIdx.x, ty = threadIdx.y;
#pragma unroll
    for (int i = 0; i < 4; i++)
        tile[ty + i * 8][tx] = W[(size_t)(k0 + ty + i * 8) * 1024 + c0 + tx];
    __syncthreads();
#pragma unroll
    for (int i = 0; i < 4; i++) {
        int rr = ty + i * 8;
        g_wt[(size_t)(n0 + rr) * 1024 + k0 + tx] = __float2half(tile[tx][rr]);
    }
}

// =================================================================
// HMMA GEMM core (fp16 single-term, cp.async double-buffered):
// C(128x128 f32) = A @ B^T ; A [m][k], B [n][k], both fp16.
// =================================================================
#define SK 40                       // smem row stride in fp16 (80B)
#define TILE_BYTES  (128 * SK * 2)  // 10240
#define STAGE_BYTES (2 * TILE_BYTES)

__device__ __forceinline__ void gemm_prefetch(
    const __half* __restrict__ A, const __half* __restrict__ B,
    int m0, int n0row, int k0, u32 st, int row, int half)
{
    const u32 cpo = (u32)(row * SK + half * 16) * 2;
    const size_t ga = (size_t)(m0 + row) * 1024 + k0 + half * 16;
    const size_t gn = (size_t)(n0row + row) * 1024 + k0 + half * 16;
    cpa16(st + cpo,                   A + ga);
    cpa16(st + cpo + 16,              A + ga + 8);
    cpa16(st + TILE_BYTES + cpo,      B + gn);
    cpa16(st + TILE_BYTES + cpo + 16, B + gn + 8);
    cp_commit();
}

__device__ __forceinline__ void hmma_core(
    const __half* __restrict__ A, const __half* __restrict__ B,
    int m0, int n0row, __half* sm, float acc[2][8][4])
{
    const int tid = threadIdx.x;
    const int lane = tid & 31, wid = tid >> 5;
    const int wm = wid >> 1, wn = wid & 1;
    const int lrow = lane & 15, lcol = (lane >> 4) << 3;
    const int row = tid >> 1, half = tid & 1;

    const u32 sb = smem_u32(sm);
    const u32 aoff = (u32)((wm * 32 + lrow) * SK + lcol) * 2;
    const u32 boff = (u32)((wn * 64 + lrow) * SK + lcol) * 2;

    gemm_prefetch(A, B, m0, n0row, 0, sb, row, half);

    for (int c = 0; c < 32; ++c) {
        cp_wait0();
        __syncthreads();
        if (c + 1 < 32)
            gemm_prefetch(A, B, m0, n0row, (c + 1) * 32,
                          sb + ((c + 1) & 1) * STAGE_BYTES, row, half);

        const u32 st = sb + (c & 1) * STAGE_BYTES;
        const u32 aB = st + aoff, bB = st + TILE_BYTES + boff;
#pragma unroll
        for (int ks = 0; ks < 2; ++ks) {
            const u32 kofs = ks * 32;
            u32 a2[2][4];
            ldmx4(a2[0], aB + kofs);
            ldmx4(a2[1], aB + 16 * SK * 2 + kofs);
#pragma unroll
            for (int hf = 0; hf < 2; ++hf) {
                const u32 ho = hf * 32 * SK * 2;
                u32 b2[2][4];
                ldmx4(b2[0], bB + ho + kofs);
                ldmx4(b2[1], bB + ho + 16 * SK * 2 + kofs);
#pragma unroll
                for (int mi = 0; mi < 2; ++mi)
#pragma unroll
                    for (int jj = 0; jj < 4; ++jj) {
                        const int jb = jj >> 1, sl = jj & 1;
                        mma_f16(acc[mi][hf * 4 + jj], a2[mi],
                                b2[jb][sl], b2[jb][sl + 2]);
                    }
            }
        }
    }
}

// =================================================================
// QKV GEMM: write q/k/v fp16 [B,H,S,DH]; q scaled 0.125*log2(e)
// =================================================================
__global__ __launch_bounds__(256, 2) void qkv_hmma()
{
    extern __shared__ __half dynsm[];
    const int m0 = blockIdx.x * 128;
    const int n0 = blockIdx.y * 128;          // 0..3071

    float acc[2][8][4] = {};
    hmma_core(g_x, g_wt, m0, n0, dynsm, acc);

    const int tid = threadIdx.x, lane = tid & 31, wid = tid >> 5;
    const int wm = wid >> 1, wn = wid & 1;
    const int gid = lane >> 2, tig = lane & 3;
    const int which = n0 >> 10;
    __half* __restrict__ op = (which == 0) ? g_q : (which == 1) ? g_k : g_v;
    const float sc = (which == 0) ? 0.125f * 1.4426950408889634f : 1.0f;
    const int nl0 = (n0 & 1023) + wn * 64;

#pragma unroll
    for (int mi = 0; mi < 2; ++mi) {
        const int r = m0 + wm * 32 + mi * 16 + gid;
        const int b = r >> 11, s = r & (S_ - 1);
#pragma unroll
        for (int j = 0; j < 8; ++j) {
            const int nl = nl0 + j * 8 + tig * 2;
            const int h = nl >> 6, d = nl & 63;
            const size_t base = ((size_t)(b * H_ + h) * S_ + s) * DH_ + d;
            *(u32*)(op + base)           = pkhf(acc[mi][j][0] * sc, acc[mi][j][1] * sc);
            *(u32*)(op + base + 8 * DH_) = pkhf(acc[mi][j][2] * sc, acc[mi][j][3] * sc);
        }
    }
}

// =================================================================
// Output projection + residual: g_res = ctx @ W_O + x
// =================================================================
__global__ __launch_bounds__(256, 2) void proj_hmma(const float* __restrict__ x)
{
    extern __shared__ __half dynsm[];
    const int m0 = blockIdx.x * 128;
    const int n0 = blockIdx.y * 128;          // 0..1023

    float acc[2][8][4] = {};
    hmma_core(g_cx, g_wt, m0, n0 + 3072, dynsm, acc);

    const int tid = threadIdx.x, lane = tid & 31, wid = tid >> 5;
    const int wm = wid >> 1, wn = wid & 1;
    const int gid = lane >> 2, tig = lane & 3;
    const int nb = n0 + wn * 64;

#pragma unroll
    for (int mi = 0; mi < 2; ++mi) {
        const size_t r = m0 + wm * 32 + mi * 16 + gid;
#pragma unroll
        for (int j = 0; j < 8; ++j) {
            const size_t n = nb + j * 8 + tig * 2;
            float2 x0 = *(const float2*)(x + r * D_ + n);
            float2 x1 = *(const float2*)(x + (r + 8) * D_ + n);
            *(float2*)(g_res + r * D_ + n) =
                make_float2(acc[mi][j][0] + x0.x, acc[mi][j][1] + x0.y);
            *(float2*)(g_res + (r + 8) * D_ + n) =
                make_float2(acc[mi][j][2] + x1.x, acc[mi][j][3] + x1.y);
        }
    }
}

// =================================================================
// Flash attention (fp16 HMMA, causal, exp2 domain).
// Block = 64 queries / 4 warps; heavy blocks (large qt) launch first.
// Softmax: packed-f16 max shuffles (m cancels exactly in softmax);
// l kept as per-lane partials, quad-reduced once at the end.
// =================================================================
#define SKA 72

__global__ __launch_bounds__(128, 4) void attn_hmma()
{
    __shared__ __align__(16) __half smK[64 * SKA];
    __shared__ __align__(16) __half smV[64 * SKA];

    const int tid = threadIdx.x, lane = tid & 31, wm = tid >> 5;
    const int qt = gridDim.x - 1 - blockIdx.x;   // heavy blocks first
    const int bh = blockIdx.y;
    const int q0 = qt * 64;
    const size_t gb = (size_t)bh * S_ * DH_;
    const u32 sbK = smem_u32(smK), sbV = smem_u32(smV);

    // ---- stage Q (fp16) into smK, extract per-warp A fragments
    {
        const int row = tid >> 1, c = (tid & 1) * 32;
        const uint4* s = (const uint4*)(g_q + gb + (size_t)(q0 + row) * DH_ + c);
        uint4* d = (uint4*)(smK + row * SKA + c);
#pragma unroll
        for (int i = 0; i < 4; i++) d[i] = s[i];
    }
    __syncthreads();
    u32 qf[4][4];
    {
        const u32 off = ((wm * 16 + (lane & 15)) * SKA + (lane >> 4) * 8) * 2;
#pragma unroll
        for (int ks = 0; ks < 4; ks++)
            ldmx4(qf[ks], sbK + off + ks * 32);
    }
    __syncthreads();

    float o[8][4] = {};
    float mA = -1e30f, mB = -1e30f, lA = 0.f, lB = 0.f;   // l: per-lane partial
    const int rowA = q0 + wm * 16 + (lane >> 2);
    const u32 sboff = ((lane & 15) * SKA + (lane >> 4) * 8) * 2;
    const u32 vtoff = ((((lane >> 3) & 1) * 8 + (lane & 7)) * SKA + (lane >> 4) * 8) * 2;

    for (int kt = 0; kt <= qt; ++kt) {
        const int k0t = kt * 64;
        {   // load K/V tiles (64x64 fp16 each), 128 threads
            const int row = tid >> 1, c = (tid & 1) * 32;
            const size_t g = gb + (size_t)(k0t + row) * DH_ + c;
            const uint4* s0 = (const uint4*)(g_k + g);
            const uint4* s1 = (const uint4*)(g_v + g);
            uint4* d0 = (uint4*)(smK + row * SKA + c);
            uint4* d1 = (uint4*)(smV + row * SKA + c);
#pragma unroll
            for (int i = 0; i < 4; i++) { d0[i] = s0[i]; d1[i] = s1[i]; }
        }
        __syncthreads();

        if (k0t <= q0 + wm * 16 + 15) {   // warp-uniform: skip fully-masked tiles
            // ---- S = Q K^T, f32 accum
            float s[8][4] = {};
#pragma unroll
            for (int ks = 0; ks < 4; ks++)
#pragma unroll
                for (int g = 0; g < 4; g++) {
                    u32 k4[4];
                    ldmx4(k4, sbK + sboff + g * 16 * SKA * 2 + ks * 32);
                    mma_f16(s[2 * g],     qf[ks], k4[0], k4[2]);
                    mma_f16(s[2 * g + 1], qf[ks], k4[1], k4[3]);
                }

            // ---- causal mask (diagonal tiles only)
            if (k0t + 63 > q0 + wm * 16) {
#pragma unroll
                for (int b = 0; b < 8; b++) {
                    int cb = k0t + b * 8 + (lane & 3) * 2;
                    if (cb > rowA)         s[b][0] = -1e30f;
                    if (cb + 1 > rowA)     s[b][1] = -1e30f;
                    if (cb > rowA + 8)     s[b][2] = -1e30f;
                    if (cb + 1 > rowA + 8) s[b][3] = -1e30f;
                }
            }

            // ---- online softmax (exp2 domain); packed-f16 quad max
            float tA = fmaxf(s[0][0], s[0][1]), tB = fmaxf(s[0][2], s[0][3]);
#pragma unroll
            for (int b = 1; b < 8; b++) {
                tA = fmaxf(tA, fmaxf(s[b][0], s[b][1]));
                tB = fmaxf(tB, fmaxf(s[b][2], s[b][3]));
            }
            {
                __half2 mm = __floats2half2_rn(tA, tB);
                __half2 s1 = __shfl_xor_sync(~0u, mm, 1);
                mm = __hmax2(mm, s1);
                __half2 s2 = __shfl_xor_sync(~0u, mm, 2);
                mm = __hmax2(mm, s2);
                float2 mf = __half22float2(mm);
                tA = mf.x; tB = mf.y;
            }
            float nmA = fmaxf(mA, tA), nmB = fmaxf(mB, tB);
            float alA = ex2f(mA - nmA), alB = ex2f(mB - nmB);
            mA = nmA; mB = nmB;
#pragma unroll
            for (int b = 0; b < 8; b++) {
                o[b][0] *= alA; o[b][1] *= alA;
                o[b][2] *= alB; o[b][3] *= alB;
            }

            // ---- P = exp2(S-m) fp16, PV per kstep; per-lane l partials
            float sumA = 0.f, sumB = 0.f;
#pragma unroll
            for (int ks = 0; ks < 4; ks++) {
                float p[8];
                p[0] = ex2f(s[2 * ks][0] - mA);     p[1] = ex2f(s[2 * ks][1] - mA);
                p[2] = ex2f(s[2 * ks][2] - mB);     p[3] = ex2f(s[2 * ks][3] - mB);
                p[4] = ex2f(s[2 * ks + 1][0] - mA); p[5] = ex2f(s[2 * ks + 1][1] - mA);
                p[6] = ex2f(s[2 * ks + 1][2] - mB); p[7] = ex2f(s[2 * ks + 1][3] - mB);
                sumA += p[0] + p[1] + p[4] + p[5];
                sumB += p[2] + p[3] + p[6] + p[7];
                u32 ph4[4];
                ph4[0] = pkhf(p[0], p[1]); ph4[1] = pkhf(p[2], p[3]);
                ph4[2] = pkhf(p[4], p[5]); ph4[3] = pkhf(p[6], p[7]);
#pragma unroll
                for (int g = 0; g < 4; g++) {
                    u32 v4[4];
                    ldmx4t(v4, sbV + vtoff + ks * 16 * SKA * 2 + g * 32);
                    mma_f16(o[2 * g],     ph4, v4[0], v4[1]);
                    mma_f16(o[2 * g + 1], ph4, v4[2], v4[3]);
                }
            }
            lA = lA * alA + sumA;    // per-lane partial; quad-reduced at end
            lB = lB * alB + sumB;
        }
        __syncthreads();
    }

    // ---- final quad reduction of l, then write ctx fp16
    lA += __shfl_xor_sync(~0u, lA, 1);
    lA += __shfl_xor_sync(~0u, lA, 2);
    lB += __shfl_xor_sync(~0u, lB, 1);
    lB += __shfl_xor_sync(~0u, lB, 2);
    const float iA = 1.0f / lA, iB = 1.0f / lB;
    const int bb = bh >> 4, hh = bh & 15;
    const size_t m0r = (size_t)(bb * S_ + rowA) * D_ + hh * 64;
    const size_t m1r = m0r + 8 * D_;
#pragma unroll
    for (int b = 0; b < 8; b++) {
        int col = b * 8 + (lane & 3) * 2;
        *(u32*)(g_cx + m0r + col) = pkhf(o[b][0] * iA, o[b][1] * iA);
        *(u32*)(g_cx + m1r + col) = pkhf(o[b][2] * iB, o[b][3] * iB);
    }
}

// =================================================================
// LayerNorm over last dim (1024)
// =================================================================
__global__ __launch_bounds__(256) void ln_kernel(
    const float* __restrict__ gamma,
    const float* __restrict__ beta,
    float* __restrict__ out)
{
    __shared__ float ws[8], wq2[8];
    const int row = blockIdx.x;
    const int t = threadIdx.x;
    const int lane = t & 31, w = t >> 5;
    const float* rp = g_res + (size_t)row * D_;

    float4 v = *(const float4*)(rp + t * 4);
    float s = v.x + v.y + v.z + v.w;
    float q = v.x * v.x + v.y * v.y + v.z * v.z + v.w * v.w;
#pragma unroll
    for (int o = 16; o > 0; o >>= 1) {
        s += __shfl_xor_sync(0xffffffffu, s, o);
        q += __shfl_xor_sync(0xffffffffu, q, o);
    }
    if (lane == 0) { ws[w] = s; wq2[w] = q; }
    __syncthreads();
    float S = 0.f, Q = 0.f;
#pragma unroll
    for (int i = 0; i < 8; i++) { S += ws[i]; Q += wq2[i]; }

    float mu  = S * (1.0f / 1024.0f);
    float var = Q * (1.0f / 1024.0f) - mu * mu;
    float rstd = rsqrtf(var + 1e-5f);

    float4 g  = *(const float4*)(gamma + t * 4);
    float4 bt = *(const float4*)(beta  + t * 4);
    float4 o4;
    o4.x = (v.x - mu) * rstd * g.x + bt.x;
    o4.y = (v.y - mu) * rstd * g.y + bt.y;
    o4.z = (v.z - mu) * rstd * g.z + bt.z;
    o4.w = (v.w - mu) * rstd * g.w + bt.w;
    *(float4*)(out + (size_t)row * D_ + t * 4) = o4;
}

// =================================================================
extern "C" void kernel_launch(void* const* d_in, const int* in_sizes, int n_in,
                              void* d_out, int out_size)
{
    const float* x     = (const float*)d_in[0];
    const float* wq    = (const float*)d_in[1];
    const float* wk    = (const float*)d_in[2];
    const float* wv    = (const float*)d_in[3];
    const float* wo    = (const float*)d_in[4];
    const float* gamma = (const float*)d_in[5];
    const float* beta  = (const float*)d_in[6];
    float* out = (float*)d_out;

    const int gemm_smem = 2 * STAGE_BYTES;   // 40 KB double-buffered
    cudaFuncSetAttribute(qkv_hmma,
                         cudaFuncAttributeMaxDynamicSharedMemorySize, gemm_smem);
    cudaFuncSetAttribute(proj_hmma,
                         cudaFuncAttributeMaxDynamicSharedMemorySize, gemm_smem);

    cvt_x<<<M_, 256>>>(x);
    wt_t<<<dim3(32, 128), dim3(32, 8)>>>(wq, wk, wv, wo);
    qkv_hmma<<<dim3(M_ / 128, 3072 / 128), 256, gemm_smem>>>();
    attn_hmma<<<dim3(S_ / 64, B_ * H_), 128>>>();
    proj_hmma<<<dim3(M_ / 128, D_ / 128), 256, gemm_smem>>>(x);
    ln_kernel<<<M_, 256>>>(gamma, beta, out);
}